// round 8
// baseline (speedup 1.0000x reference)
#include <cuda_runtime.h>

#define BDIM 4096   // batch
#define IDIM 4096   // in features
#define ODIM 4096   // out features

// Scratch (allocation-free rule: __device__ globals; zero-init at module load)
__device__ float        g_wsb[ODIM];  // bias[o] * sum_i weight[o,i]
__device__ unsigned int g_cnt;        // weight rows completed (producer count)
__device__ unsigned int g_done;       // consumer blocks past the gate (for reset)

// ---------------------------------------------------------------------------
// Single mega-kernel, 8192 blocks x 128 threads.
//   bid <  ODIM : producer — weight row sum * bias -> g_wsb, release-count.
//   bid >= ODIM : consumer — input row sum (loads issued immediately, so input
//                 reads overlap weight reads), acquire-spin until all wsb
//                 ready, then stream the output row.
// Weight blocks occupy the first scheduling waves, so the gate opens early;
// consumer store traffic then overlaps remaining consumer read traffic,
// keeping DRAM continuously busy with no kernel-boundary bubble.
//
// Replay hygiene: the LAST consumer block to pass the gate (g_done counter)
// resets g_cnt/g_done to 0 for the next graph replay. By construction no
// block can still be spinning on g_cnt at that point (every other consumer
// already passed the gate before incrementing g_done).
// ---------------------------------------------------------------------------
__global__ __launch_bounds__(128) void mega_kernel(
    const float* __restrict__ input,
    const float* __restrict__ weight,
    const float* __restrict__ bias,
    float* __restrict__ out)
{
    const int bid = blockIdx.x;
    const int tid = threadIdx.x;

    __shared__ float warp_sums[4];
    __shared__ float xs_sh;

    if (bid < ODIM) {
        // ---------------- producer: weight row ----------------
        const float4* src = reinterpret_cast<const float4*>(
            weight + (size_t)bid * IDIM);

        float4 v[8];
#pragma unroll
        for (int i = 0; i < 8; i++) v[i] = __ldcs(&src[tid + i * 128]);

        float s = 0.0f;
#pragma unroll
        for (int i = 0; i < 8; i++) s += (v[i].x + v[i].y) + (v[i].z + v[i].w);

#pragma unroll
        for (int off = 16; off > 0; off >>= 1)
            s += __shfl_down_sync(0xFFFFFFFFu, s, off);

        if ((tid & 31) == 0) warp_sums[tid >> 5] = s;
        __syncthreads();

        if (tid == 0) {
            float total = (warp_sums[0] + warp_sums[1]) +
                          (warp_sums[2] + warp_sums[3]);
            g_wsb[bid] = total * __ldg(&bias[bid]);
            __threadfence();              // release g_wsb before counting
            atomicAdd(&g_cnt, 1u);
        }
    } else {
        // ---------------- consumer: input row -> output row ----------------
        const int row = bid - ODIM;
        const float4* src = reinterpret_cast<const float4*>(
            input + (size_t)row * IDIM);

        // Loads fire immediately — overlap with producer weight reads.
        float4 v[8];
#pragma unroll
        for (int i = 0; i < 8; i++) v[i] = __ldcs(&src[tid + i * 128]);

        float s = 0.0f;
#pragma unroll
        for (int i = 0; i < 8; i++) s += (v[i].x + v[i].y) + (v[i].z + v[i].w);

#pragma unroll
        for (int off = 16; off > 0; off >>= 1)
            s += __shfl_down_sync(0xFFFFFFFFu, s, off);

        if ((tid & 31) == 0) warp_sums[tid >> 5] = s;
        __syncthreads();
        if (tid == 0)
            xs_sh = (warp_sums[0] + warp_sums[1]) +
                    (warp_sums[2] + warp_sums[3]);

        // Gate: wait until all ODIM producers have released their wsb entry.
        if (tid == 0) {
            unsigned int c;
            do {
                asm volatile("ld.global.acquire.gpu.u32 %0, [%1];"
                             : "=r"(c) : "l"(&g_cnt));
                if (c >= (unsigned)ODIM) break;
                __nanosleep(64);
            } while (true);
        }
        __syncthreads();     // broadcasts gate + xs_sh; CTA-scope fence chains
                             // the tid0 acquire to all threads' wsb loads
        const float xs = xs_sh;

        // Store phase: out[row, o] = xs * bias[o] + wsb[o]
        float4* dst = reinterpret_cast<float4*>(out + (size_t)row * ODIM);
        const float4* bi4 = reinterpret_cast<const float4*>(bias);
        const float4* ws4 = reinterpret_cast<const float4*>(g_wsb);

#pragma unroll
        for (int i = 0; i < 8; i++) {
            const int c = tid + i * 128;
            float4 b = bi4[c];
            float4 w = ws4[c];
            float4 r;
            r.x = fmaf(xs, b.x, w.x);
            r.y = fmaf(xs, b.y, w.y);
            r.z = fmaf(xs, b.z, w.z);
            r.w = fmaf(xs, b.w, w.w);
            __stcs(&dst[c], r);
        }

        // Replay hygiene: last consumer past the gate resets both counters.
        if (tid == 0) {
            unsigned int old = atomicAdd(&g_done, 1u);
            if (old == (unsigned)(BDIM - 1)) {
                g_cnt  = 0u;   // no block can still be spinning on g_cnt here
                g_done = 0u;
                __threadfence();
            }
        }
    }
}

extern "C" void kernel_launch(void* const* d_in, const int* in_sizes, int n_in,
                              void* d_out, int out_size)
{
    const float* input  = (const float*)d_in[0];
    const float* weight = (const float*)d_in[1];
    const float* bias   = (const float*)d_in[2];
    float* out = (float*)d_out;

    mega_kernel<<<ODIM + BDIM, 128>>>(input, weight, bias, out);
}